// round 14
// baseline (speedup 1.0000x reference)
#include <cuda_runtime.h>
#include <cuda_bf16.h>
#include <math.h>
#include <stdint.h>

// ---------------- problem constants ----------------
#define BATCH  128
#define LSEQ   16
#define EMB    768
#define DHALF  384
#define HEADS  12
#define HDIM   64
#define NL     6
#define SEQ    12
#define NLIDX  15
#define FF     3072
#define TOK    (NLIDX * BATCH * SEQ)        // 23040
#define TE     (TOK * EMB)                  // 17694720

#define WQKV   (EMB * EMB)                  // 589824
#define WFFN   (EMB * FF)                   // 2359296
#define WLAYER (4 * WQKV + 2 * WFFN)        // 7077888
#define NQKV   (3 * EMB)                    // 2304

// GEMM tiling: 128x256 tile, BK=32, 3-stage cp.async pipeline, 512 threads
#define BM 128
#define BN 256
#define BKT 32
// stage: Ah 12288 + Al 12288 + Bh 24576 + Bl 24576 = 73728
#define STAGE_BYTES 73728
#define NSTAGE 3
#define DSMEM_BYTES (NSTAGE * STAGE_BYTES)   // 221184

// ---------------- scratch (device globals; no cudaMalloc allowed) ----------------
__device__ float g_x[TE];                          // fp32 residual stream
__device__ float g_qkv[(size_t)TOK * NQKV];        // fused qkv output (fp32)
__device__ __nv_bfloat16 g_ah[(size_t)TOK * EMB];  // 768-wide GEMM input hi
__device__ __nv_bfloat16 g_al[(size_t)TOK * EMB];  // 768-wide GEMM input lo
__device__ __nv_bfloat16 g_afh[(size_t)TOK * FF];  // 3072-wide GEMM input hi
__device__ __nv_bfloat16 g_afl[(size_t)TOK * FF];  // 3072-wide GEMM input lo
__device__ __nv_bfloat16 g_wh[(size_t)NL * WLAYER];// transposed weights hi  [N][K]
__device__ __nv_bfloat16 g_wl[(size_t)NL * WLAYER];// transposed weights lo
__device__ float g_bqkv[NL * NQKV];
__device__ float g_logits[NLIDX * BATCH * 3];
__device__ float g_losses[NLIDX];

// ---------------- helpers ----------------
static __device__ __forceinline__ unsigned int smem_u32(const void* p) {
    unsigned int a;
    asm("{ .reg .u64 t; cvta.to.shared.u64 t, %1; cvt.u32.u64 %0, t; }"
        : "=r"(a) : "l"(p));
    return a;
}
static __device__ __forceinline__ void cp16(unsigned int dst, const void* src) {
    asm volatile("cp.async.cg.shared.global [%0], [%1], 16;" :: "r"(dst), "l"(src));
}
static __device__ __forceinline__ void cp_commit() {
    asm volatile("cp.async.commit_group;" ::: "memory");
}
static __device__ __forceinline__ void cp_wait1() {
    asm volatile("cp.async.wait_group 1;" ::: "memory");
}
static __device__ __forceinline__ void cp_wait0() {
    asm volatile("cp.async.wait_group 0;" ::: "memory");
}
static __device__ __forceinline__ void ldsm4(unsigned int* r, unsigned int addr) {
    asm volatile("ldmatrix.sync.aligned.m8n8.x4.shared.b16 {%0,%1,%2,%3}, [%4];"
                 : "=r"(r[0]), "=r"(r[1]), "=r"(r[2]), "=r"(r[3]) : "r"(addr));
}
static __device__ __forceinline__ void mma_bf16(float* c, const unsigned int* a,
                                                unsigned int b0, unsigned int b1) {
    asm volatile(
        "mma.sync.aligned.m16n8k16.row.col.f32.bf16.bf16.f32 "
        "{%0,%1,%2,%3}, {%4,%5,%6,%7}, {%8,%9}, {%0,%1,%2,%3};"
        : "+f"(c[0]), "+f"(c[1]), "+f"(c[2]), "+f"(c[3])
        : "r"(a[0]), "r"(a[1]), "r"(a[2]), "r"(a[3]), "r"(b0), "r"(b1));
}
static __device__ __forceinline__ void split_bf16(float v, __nv_bfloat16& h, __nv_bfloat16& l) {
    h = __float2bfloat16_rn(v);
    l = __float2bfloat16_rn(v - __bfloat162float(h));
}
static __device__ __forceinline__ unsigned int pack_bf2(__nv_bfloat16 a, __nv_bfloat16 b) {
    __nv_bfloat162 p; p.x = a; p.y = b;
    return *reinterpret_cast<unsigned int*>(&p);
}

// ---------------- batched weight transpose+split ----------------
__global__ __launch_bounds__(256) void wtrans_sq_kernel(
    const float* __restrict__ Wq, const float* __restrict__ Wk,
    const float* __restrict__ Wv, const float* __restrict__ Wo,
    __nv_bfloat16* __restrict__ hi, __nv_bfloat16* __restrict__ lo)
{
    __shared__ float tile[32][33];
    int z = blockIdx.z;
    int l = z >> 2, m = z & 3;
    const float* W = (m == 0) ? Wq : (m == 1) ? Wk : (m == 2) ? Wv : Wo;
    W += (size_t)l * WQKV;
    size_t obase = (size_t)l * WLAYER + (size_t)m * WQKV;

    int n0 = blockIdx.x * 32, k0 = blockIdx.y * 32;
    int tx = threadIdx.x & 31, ty = threadIdx.x >> 5;
#pragma unroll
    for (int j = 0; j < 4; ++j)
        tile[ty + j * 8][tx] = W[(size_t)(k0 + ty + j * 8) * EMB + n0 + tx];
    __syncthreads();
#pragma unroll
    for (int j = 0; j < 4; ++j) {
        int n = ty + j * 8;
        float v = tile[tx][n];
        __nv_bfloat16 h, l2;
        split_bf16(v, h, l2);
        size_t o = obase + (size_t)(n0 + n) * EMB + k0 + tx;
        hi[o] = h;
        lo[o] = l2;
    }
}

__global__ __launch_bounds__(256) void wtrans_f1_kernel(
    const float* __restrict__ W1, __nv_bfloat16* __restrict__ hi,
    __nv_bfloat16* __restrict__ lo)
{
    __shared__ float tile[32][33];
    int l = blockIdx.z;
    const float* W = W1 + (size_t)l * WFFN;
    size_t obase = (size_t)l * WLAYER + (size_t)4 * WQKV;

    int n0 = blockIdx.x * 32, k0 = blockIdx.y * 32;
    int tx = threadIdx.x & 31, ty = threadIdx.x >> 5;
#pragma unroll
    for (int j = 0; j < 4; ++j)
        tile[ty + j * 8][tx] = W[(size_t)(k0 + ty + j * 8) * FF + n0 + tx];
    __syncthreads();
#pragma unroll
    for (int j = 0; j < 4; ++j) {
        int n = ty + j * 8;
        float v = tile[tx][n];
        __nv_bfloat16 h, l2;
        split_bf16(v, h, l2);
        size_t o = obase + (size_t)(n0 + n) * EMB + k0 + tx;
        hi[o] = h;
        lo[o] = l2;
    }
}

__global__ __launch_bounds__(256) void wtrans_f2_kernel(
    const float* __restrict__ W2, __nv_bfloat16* __restrict__ hi,
    __nv_bfloat16* __restrict__ lo)
{
    __shared__ float tile[32][33];
    int l = blockIdx.z;
    const float* W = W2 + (size_t)l * WFFN;
    size_t obase = (size_t)l * WLAYER + (size_t)4 * WQKV + WFFN;

    int n0 = blockIdx.x * 32, k0 = blockIdx.y * 32;
    int tx = threadIdx.x & 31, ty = threadIdx.x >> 5;
#pragma unroll
    for (int j = 0; j < 4; ++j)
        tile[ty + j * 8][tx] = W[(size_t)(k0 + ty + j * 8) * EMB + n0 + tx];
    __syncthreads();
#pragma unroll
    for (int j = 0; j < 4; ++j) {
        int n = ty + j * 8;
        float v = tile[tx][n];
        __nv_bfloat16 h, l2;
        split_bf16(v, h, l2);
        size_t o = obase + (size_t)(n0 + n) * FF + k0 + tx;
        hi[o] = h;
        lo[o] = l2;
    }
}

// ---------------- input assembly (+ fused qkv bias concat in tail blocks) ----------------
#define ASM_TOTAL (TE + NL * NQKV)
__global__ __launch_bounds__(256) void assemble_kernel(
    const float* __restrict__ X, const float* __restrict__ targets,
    const float* __restrict__ omegas, const float* __restrict__ phases,
    const int* __restrict__ perms, float* __restrict__ xout,
    const float* __restrict__ bq, const float* __restrict__ bk,
    const float* __restrict__ bv, float* __restrict__ bqkv)
{
    int idx = blockIdx.x * blockDim.x + threadIdx.x;
    if (idx >= ASM_TOTAL) return;
    if (idx >= TE) {
        int k = idx - TE;
        int l = k / NQKV, n = k % NQKV;
        float v;
        if (n < EMB) v = bq[l * EMB + n];
        else if (n < 2 * EMB) v = bk[l * EMB + n - EMB];
        else v = bv[l * EMB + n - 2 * EMB];
        bqkv[k] = v;
        return;
    }
    int e = idx % EMB;
    int t = idx / EMB;
    int s = t % SEQ;
    int b = (t / SEQ) % BATCH;
    int lidx = t / (SEQ * BATCH);
    int sb = perms[lidx * BATCH + b];

    float val;
    if (s < 3) {
        int c = s;
        int ti = (e < DHALF) ? (15 - lidx) : (14 - lidx);
        int d  = (e < DHALF) ? e : (e - DHALF);
        float xv = X[(sb * LSEQ + ti) * 3 + c];
        val = cosf(xv * omegas[c * DHALF + d] + phases[c * DHALF + d]);
    } else if (s < 6) {
        int c = s - 3;
        int ti = (16 - lidx) % 16;
        val = targets[(sb * LSEQ + ti) * 3 + c];
    } else {
        val = (float)(15 - lidx);
    }
    xout[idx] = val;
}

// ---------------- layernorm: warp per token, shuffle-only reductions ----------------
__global__ __launch_bounds__(256) void ln_split_kernel(
    const float* __restrict__ in, __nv_bfloat16* __restrict__ oh,
    __nv_bfloat16* __restrict__ ol, const float* __restrict__ gam,
    const float* __restrict__ bet)
{
    int tok  = blockIdx.x * 8 + (threadIdx.x >> 5);
    int lane = threadIdx.x & 31;
    const float* x = in + (size_t)tok * EMB;

    float v[24];
    float s = 0.0f;
#pragma unroll
    for (int j = 0; j < 24; ++j) {
        v[j] = x[lane + j * 32];
        s += v[j];
    }
#pragma unroll
    for (int o = 16; o > 0; o >>= 1) s += __shfl_xor_sync(0xffffffffu, s, o);
    float mu = s * (1.0f / EMB);

    float var = 0.0f;
#pragma unroll
    for (int j = 0; j < 24; ++j) {
        v[j] -= mu;
        var += v[j] * v[j];
    }
#pragma unroll
    for (int o = 16; o > 0; o >>= 1) var += __shfl_xor_sync(0xffffffffu, var, o);
    float rs = rsqrtf(var * (1.0f / EMB) + 1e-3f);

    size_t base = (size_t)tok * EMB;
#pragma unroll
    for (int j = 0; j < 24; ++j) {
        int e = lane + j * 32;
        float r = v[j] * rs * gam[e] + bet[e];
        __nv_bfloat16 h, l;
        split_bf16(r, h, l);
        oh[base + e] = h;
        ol[base + e] = l;
    }
}

// ---------------- bf16x3 mma.sync GEMM, 128x256 tile, 512 thr, 3-stage ----------------
// C[M, Ntot] = A[M, K] @ Wt[Ntot, K]^T, all operands pre-split bf16 hi/lo.
// 16 warps as 4(m) x 4(n), warp tile 32x64. One __syncthreads per stage.
// Stage layout: Ah 0 (chunks +6144), Al 12288, Bh 24576 (chunks +12288), Bl 49152.
// EPI 0: Cf = acc + bias ; 1: Cf += acc + bias ; 2: Ch/Cl = split(relu(acc + bias))
template <int EPI>
static __device__ __forceinline__ void gemm_body(
    const __nv_bfloat16* __restrict__ Ah, const __nv_bfloat16* __restrict__ Al,
    const __nv_bfloat16* __restrict__ Bh, const __nv_bfloat16* __restrict__ Bl,
    const float* __restrict__ bias, float* __restrict__ Cf,
    __nv_bfloat16* __restrict__ Ch, __nv_bfloat16* __restrict__ Cl,
    int Ntot, int K)
{
    extern __shared__ __align__(16) char dsm[];
    const int t = threadIdx.x;
    const int lane = t & 31, wid = t >> 5;
    const int wm = wid >> 2, wn = wid & 3;
    const int row0 = blockIdx.y * BM, col0 = blockIdx.x * BN;
    const unsigned int smem = smem_u32(dsm);

    float acc[2][8][4];
#pragma unroll
    for (int i = 0; i < 2; ++i)
#pragma unroll
        for (int j = 0; j < 8; ++j)
#pragma unroll
            for (int k = 0; k < 4; ++k) acc[i][j][k] = 0.0f;

    // cp.async mapping: 512 threads, 6 cp16 each (A hi/lo at row rr; B rows rr, rr+128 hi/lo)
    const int seg   = t & 1;
    const int chunk = (t >> 1) & 1;
    const int rr    = t >> 2;                    // 0..127
    const int koff0 = chunk * 16 + seg * 8;

    auto load_stage = [&](int kt, int stg) {
        unsigned int sb = smem + stg * STAGE_BYTES;
        int koff = kt * BKT + koff0;
        // A rows
#pragma unroll
        for (int hl = 0; hl < 2; ++hl) {
            const __nv_bfloat16* src = (hl ? Al : Ah) + (size_t)(row0 + rr) * K + koff;
            cp16(sb + hl * 12288 + chunk * 6144 + rr * 48 + seg * 16, src);
        }
        // B rows
#pragma unroll
        for (int i = 0; i < 4; ++i) {
            int hl = i & 1, rh = i >> 1;
            int r = rh * 128 + rr;
            const __nv_bfloat16* src = (hl ? Bl : Bh) + (size_t)(col0 + r) * K + koff;
            cp16(sb + 24576 + hl * 24576 + chunk * 12288 + r * 48 + seg * 16, src);
        }
        cp_commit();
    };

    // ldmatrix base addresses
    const unsigned int aHb = smem + (wm * 32 + (lane & 15)) * 48 + ((lane >> 4) << 4);
    const unsigned int bHb = smem + 24576 +
        (wn * 64 + (lane & 7) + ((lane >> 4) << 3)) * 48 + (((lane >> 3) & 1) << 4);

    const int nst = K / BKT;
    load_stage(0, 0);
    load_stage(1, 1);

    for (int st = 0; st < nst; ++st) {
        if (st + 1 < nst) cp_wait1(); else cp_wait0();
        __syncthreads();
        if (st + 2 < nst) load_stage(st + 2, (st + 2) % NSTAGE);
        unsigned int so = (st % NSTAGE) * STAGE_BYTES;
#pragma unroll
        for (int ch = 0; ch < 2; ++ch) {
            unsigned int aco = so + ch * 6144;
            unsigned int bco = so + ch * 12288;
            unsigned int Bfh[4][4], Bfl[4][4];
#pragma unroll
            for (int f = 0; f < 4; ++f) {
                ldsm4(Bfh[f], bHb + bco + f * 768);
                ldsm4(Bfl[f], bHb + bco + 24576 + f * 768);
            }
#pragma unroll
            for (int mi = 0; mi < 2; ++mi) {
                unsigned int Afh[4], Afl[4];
                ldsm4(Afh, aHb + aco + mi * 768);
                ldsm4(Afl, aHb + aco + 12288 + mi * 768);
                // term-major: HH over 8 accs, then HL, then LH
#pragma unroll
                for (int f = 0; f < 4; ++f)
#pragma unroll
                    for (int q = 0; q < 2; ++q)
                        mma_bf16(acc[mi][f * 2 + q], Afh, Bfh[f][2 * q], Bfh[f][2 * q + 1]);
#pragma unroll
                for (int f = 0; f < 4; ++f)
#pragma unroll
                    for (int q = 0; q < 2; ++q)
                        mma_bf16(acc[mi][f * 2 + q], Afh, Bfl[f][2 * q], Bfl[f][2 * q + 1]);
#pragma unroll
                for (int f = 0; f < 4; ++f)
#pragma unroll
                    for (int q = 0; q < 2; ++q)
                        mma_bf16(acc[mi][f * 2 + q], Afl, Bfh[f][2 * q], Bfh[f][2 * q + 1]);
            }
        }
    }

    // ---- epilogue ----
    const int rbase = row0 + wm * 32 + (lane >> 2);
    const int cbase = col0 + wn * 64 + (lane & 3) * 2;
#pragma unroll
    for (int ni = 0; ni < 8; ++ni) {
        int cb = cbase + ni * 8;
        float2 bi = *(const float2*)&bias[cb];
#pragma unroll
        for (int mi = 0; mi < 2; ++mi) {
            float* c = acc[mi][ni];
            size_t o0 = (size_t)(rbase + mi * 16) * Ntot + cb;
            size_t o1 = o0 + (size_t)8 * Ntot;
            if (EPI == 2) {
                float v00 = fmaxf(c[0] + bi.x, 0.0f), v01 = fmaxf(c[1] + bi.y, 0.0f);
                float v10 = fmaxf(c[2] + bi.x, 0.0f), v11 = fmaxf(c[3] + bi.y, 0.0f);
                __nv_bfloat16 h00, l00, h01, l01, h10, l10, h11, l11;
                split_bf16(v00, h00, l00);
                split_bf16(v01, h01, l01);
                split_bf16(v10, h10, l10);
                split_bf16(v11, h11, l11);
                *(unsigned int*)&Ch[o0] = pack_bf2(h00, h01);
                *(unsigned int*)&Cl[o0] = pack_bf2(l00, l01);
                *(unsigned int*)&Ch[o1] = pack_bf2(h10, h11);
                *(unsigned int*)&Cl[o1] = pack_bf2(l10, l11);
            } else {
                float2 v0 = make_float2(c[0] + bi.x, c[1] + bi.y);
                float2 v1 = make_float2(c[2] + bi.x, c[3] + bi.y);
                if (EPI == 1) {
                    float2 p0 = *(float2*)&Cf[o0], p1 = *(float2*)&Cf[o1];
                    v0.x += p0.x; v0.y += p0.y;
                    v1.x += p1.x; v1.y += p1.y;
                }
                *(float2*)&Cf[o0] = v0;
                *(float2*)&Cf[o1] = v1;
            }
        }
    }
}

// plain-named wrappers
__global__ __launch_bounds__(512, 1) void gemm_ep0(
    const __nv_bfloat16* __restrict__ Ah, const __nv_bfloat16* __restrict__ Al,
    const __nv_bfloat16* __restrict__ Bh, const __nv_bfloat16* __restrict__ Bl,
    const float* __restrict__ bias, float* __restrict__ Cf,
    __nv_bfloat16* __restrict__ Ch, __nv_bfloat16* __restrict__ Cl, int Ntot, int K)
{ gemm_body<0>(Ah, Al, Bh, Bl, bias, Cf, Ch, Cl, Ntot, K); }

__global__ __launch_bounds__(512, 1) void gemm_ep1(
    const __nv_bfloat16* __restrict__ Ah, const __nv_bfloat16* __restrict__ Al,
    const __nv_bfloat16* __restrict__ Bh, const __nv_bfloat16* __restrict__ Bl,
    const float* __restrict__ bias, float* __restrict__ Cf,
    __nv_bfloat16* __restrict__ Ch, __nv_bfloat16* __restrict__ Cl, int Ntot, int K)
{ gemm_body<1>(Ah, Al, Bh, Bl, bias, Cf, Ch, Cl, Ntot, K); }

__global__ __launch_bounds__(512, 1) void gemm_ep2(
    const __nv_bfloat16* __restrict__ Ah, const __nv_bfloat16* __restrict__ Al,
    const __nv_bfloat16* __restrict__ Bh, const __nv_bfloat16* __restrict__ Bl,
    const float* __restrict__ bias, float* __restrict__ Cf,
    __nv_bfloat16* __restrict__ Ch, __nv_bfloat16* __restrict__ Cl, int Ntot, int K)
{ gemm_body<2>(Ah, Al, Bh, Bl, bias, Cf, Ch, Cl, Ntot, K); }

// ---------------- attention: reads fused qkv (stride 2304), writes hi/lo o ----------------
__global__ __launch_bounds__(192) void attn_kernel(
    const float* __restrict__ qkv, __nv_bfloat16* __restrict__ oh,
    __nv_bfloat16* __restrict__ ol)
{
    int inst = blockIdx.x;
    int h    = blockIdx.y;
    int base = inst * SEQ;
    int tid  = threadIdx.x;

    __shared__ float qs[SEQ][HDIM], ks[SEQ][HDIM], vs[SEQ][HDIM];
    __shared__ float sc[SEQ][SEQ], ps[SEQ][SEQ];

    for (int idx = tid; idx < SEQ * HDIM; idx += 192) {
        int s = idx >> 6, d = idx & 63;
        size_t g = (size_t)(base + s) * NQKV + h * HDIM + d;
        qs[s][d] = qkv[g];
        ks[s][d] = qkv[g + EMB];
        vs[s][d] = qkv[g + 2 * EMB];
    }
    __syncthreads();

    if (tid < SEQ * SEQ) {
        int i = tid / SEQ, j = tid % SEQ;
        float a = 0.0f;
#pragma unroll
        for (int d = 0; d < HDIM; ++d) a += qs[i][d] * ks[j][d];
        sc[i][j] = a * 0.125f;
    }
    __syncthreads();

    if (tid < SEQ) {
        float mx = -1e30f;
#pragma unroll
        for (int j = 0; j < SEQ; ++j) mx = fmaxf(mx, sc[tid][j]);
        float sum = 0.0f;
#pragma unroll
        for (int j = 0; j < SEQ; ++j) { float ev = expf(sc[tid][j] - mx); ps[tid][j] = ev; sum += ev; }
        float inv = 1.0f / sum;
#pragma unroll
        for (int j = 0; j < SEQ; ++j) ps[tid][j] *= inv;
    }
    __syncthreads();

    for (int idx = tid; idx < SEQ * HDIM; idx += 192) {
        int i = idx >> 6, d = idx & 63;
        float a = 0.0f;
#pragma unroll
        for (int j = 0; j < SEQ; ++j) a += ps[i][j] * vs[j][d];
        __nv_bfloat16 hh, ll;
        split_bf16(a, hh, ll);
        size_t g = (size_t)(base + i) * EMB + h * HDIM + d;
        oh[g] = hh;
        ol[g] = ll;
    }
}

// ---------------- output projection (reads hi+lo reconstructed) ----------------
__global__ __launch_bounds__(256) void outproj_kernel(
    const __nv_bfloat16* __restrict__ hh, const __nv_bfloat16* __restrict__ hl,
    const float* __restrict__ Wout, const float* __restrict__ bout,
    float* __restrict__ logits)
{
    __shared__ float r0[256], r1[256], r2[256];
    int inst = blockIdx.x;
    int tid = threadIdx.x;
    size_t base = (size_t)inst * (SEQ * EMB);
    float a0 = 0, a1 = 0, a2 = 0;
    for (int kk = tid; kk < SEQ * EMB; kk += 256) {
        float x = __bfloat162float(hh[base + kk]) + __bfloat162float(hl[base + kk]);
        const float* w = Wout + kk * 3;
        a0 += x * w[0]; a1 += x * w[1]; a2 += x * w[2];
    }
    r0[tid] = a0; r1[tid] = a1; r2[tid] = a2;
    __syncthreads();
    for (int s = 128; s > 0; s >>= 1) {
        if (tid < s) { r0[tid] += r0[tid + s]; r1[tid] += r1[tid + s]; r2[tid] += r2[tid + s]; }
        __syncthreads();
    }
    if (tid == 0) {
        logits[inst * 3 + 0] = r0[0] + bout[0];
        logits[inst * 3 + 1] = r1[0] + bout[1];
        logits[inst * 3 + 2] = r2[0] + bout[2];
    }
}

// ---------------- greedy matching + loss ----------------
__global__ __launch_bounds__(1024) void match_kernel(
    const float* __restrict__ logits, const float* __restrict__ targets,
    float* __restrict__ losses)
{
    extern __shared__ unsigned long long keys[];
    __shared__ int rowm[BATCH];
    __shared__ unsigned long long warpmin[32];
    __shared__ float red[1024];

    int lidx = blockIdx.x;
    int tid = threadIdx.x;
    int tref = 15 - lidx;
    const float* lg = logits + lidx * BATCH * 3;

    for (int e = tid; e < BATCH * BATCH; e += 1024) {
        int i = e >> 7, j = e & 127;
        float dx = lg[i * 3 + 0] - targets[(j * LSEQ + tref) * 3 + 0];
        float dy = lg[i * 3 + 1] - targets[(j * LSEQ + tref) * 3 + 1];
        float dz = lg[i * 3 + 2] - targets[(j * LSEQ + tref) * 3 + 2];
        float c = sqrtf(dx * dx + dy * dy + dz * dz + 1e-12f);
        keys[e] = ((unsigned long long)__float_as_uint(c) << 32) | (unsigned int)e;
    }
    __syncthreads();

    for (int r = 0; r < BATCH; ++r) {
        unsigned long long m = ~0ull;
        for (int e = tid; e < BATCH * BATCH; e += 1024) {
            unsigned long long kk = keys[e];
            m = (kk < m) ? kk : m;
        }
#pragma unroll
        for (int o = 16; o > 0; o >>= 1) {
            unsigned long long other = __shfl_down_sync(0xffffffffu, m, o);
            m = (other < m) ? other : m;
        }
        if ((tid & 31) == 0) warpmin[tid >> 5] = m;
        __syncthreads();
        if (tid < 32) {
            unsigned long long mm = warpmin[tid];
#pragma unroll
            for (int o = 16; o > 0; o >>= 1) {
                unsigned long long other = __shfl_down_sync(0xffffffffu, mm, o);
                mm = (other < mm) ? other : mm;
            }
            if (tid == 0) warpmin[0] = mm;
        }
        __syncthreads();
        unsigned long long best = warpmin[0];
        int e = (int)(best & 0xffffffffull);
        int bi = e >> 7, bj = e & 127;
        if (tid < BATCH) {
            keys[bi * BATCH + tid] = ~0ull;
            keys[tid * BATCH + bj] = ~0ull;
        }
        if (tid == 0) rowm[bi] = bj;
        __syncthreads();
    }

    float part = 0.0f;
    if (tid < BATCH * 3) {
        int i = tid / 3, c = tid % 3;
        float d = lg[rowm[i] * 3 + c] - targets[(i * LSEQ + tref) * 3 + c];
        part = d * d;
    }
    red[tid] = part;
    __syncthreads();
    for (int s = 512; s > 0; s >>= 1) {
        if (tid < s) red[tid] += red[tid + s];
        __syncthreads();
    }
    if (tid == 0) losses[lidx] = red[0] * (1.0f / (BATCH * 3));
}

__global__ void final_mean_kernel(const float* __restrict__ losses, float* __restrict__ out)
{
    if (threadIdx.x == 0 && blockIdx.x == 0) {
        float s = 0.0f;
        for (int i = 0; i < NLIDX; ++i) s += losses[i];
        out[0] = s * (1.0f / NLIDX);
    }
}

// ---------------- launch ----------------
extern "C" void kernel_launch(void* const* d_in, const int* in_sizes, int n_in,
                              void* d_out, int out_size)
{
    (void)in_sizes; (void)n_in; (void)out_size;
    const float* X    = (const float*)d_in[0];
    const float* tg   = (const float*)d_in[1];
    const float* om   = (const float*)d_in[2];
    const float* ph   = (const float*)d_in[3];
    const int*   pm   = (const int*)  d_in[4];
    const float* Wq   = (const float*)d_in[5];
    const float* bq   = (const float*)d_in[6];
    const float* Wk   = (const float*)d_in[7];
    const float* bk   = (const float*)d_in[8];
    const float* Wv   = (const float*)d_in[9];
    const float* bv   = (const float*)d_in[10];
    const float* Wo   = (const float*)d_in[11];
    const float* bo   = (const float*)d_in[12];
    const float* l1g  = (const float*)d_in[13];
    const float* l1b  = (const float*)d_in[14];
    const float* l2g  = (const float*)d_in[15];
    const float* l2b  = (const float*)d_in[16];
    const float* W1   = (const float*)d_in[17];
    const float* b1   = (const float*)d_in[18];
    const float* W2   = (const float*)d_in[19];
    const float* b2   = (const float*)d_in[20];
    const float* lfg  = (const float*)d_in[21];
    const float* lfb  = (const float*)d_in[22];
    const float* Wout = (const float*)d_in[23];
    const float* bout = (const float*)d_in[24];

    float *px, *pqkv, *pbqkv, *plog, *plos;
    __nv_bfloat16 *pah, *pal, *pafh, *pafl, *pwh, *pwl;
    cudaGetSymbolAddress((void**)&px,    g_x);
    cudaGetSymbolAddress((void**)&pqkv,  g_qkv);
    cudaGetSymbolAddress((void**)&pbqkv, g_bqkv);
    cudaGetSymbolAddress((void**)&plog,  g_logits);
    cudaGetSymbolAddress((void**)&plos,  g_losses);
    cudaGetSymbolAddress((void**)&pah,   g_ah);
    cudaGetSymbolAddress((void**)&pal,   g_al);
    cudaGetSymbolAddress((void**)&pafh,  g_afh);
    cudaGetSymbolAddress((void**)&pafl,  g_afl);
    cudaGetSymbolAddress((void**)&pwh,   g_wh);
    cudaGetSymbolAddress((void**)&pwl,   g_wl);

    cudaFuncSetAttribute(match_kernel, cudaFuncAttributeMaxDynamicSharedMemorySize, 131072);
    cudaFuncSetAttribute(gemm_ep0, cudaFuncAttributeMaxDynamicSharedMemorySize, DSMEM_BYTES);
    cudaFuncSetAttribute(gemm_ep1, cudaFuncAttributeMaxDynamicSharedMemorySize, DSMEM_BYTES);
    cudaFuncSetAttribute(gemm_ep2, cudaFuncAttributeMaxDynamicSharedMemorySize, DSMEM_BYTES);

    // prep
    wtrans_sq_kernel<<<dim3(EMB / 32, EMB / 32, NL * 4), 256>>>(Wq, Wk, Wv, Wo, pwh, pwl);
    wtrans_f1_kernel<<<dim3(FF / 32, EMB / 32, NL), 256>>>(W1, pwh, pwl);
    wtrans_f2_kernel<<<dim3(EMB / 32, FF / 32, NL), 256>>>(W2, pwh, pwl);
    assemble_kernel<<<(ASM_TOTAL + 255) / 256, 256>>>(X, tg, om, ph, pm, px, bq, bk, bv, pbqkv);

    dim3 gQKV(NQKV / BN, TOK / BM);   // (9, 180)
    dim3 gE(EMB / BN, TOK / BM);      // (3, 180)
    dim3 gF(FF / BN, TOK / BM);       // (12, 180)
    for (int l = 0; l < NL; ++l) {
        size_t base = (size_t)l * WLAYER;
        ln_split_kernel<<<TOK / 8, 256>>>(px, pah, pal, l1g + l * EMB, l1b + l * EMB);
        gemm_ep0<<<gQKV, 512, DSMEM_BYTES>>>(pah, pal, pwh + base, pwl + base,
                                             pbqkv + l * NQKV, pqkv, pafh, pafl, NQKV, EMB);
        attn_kernel<<<dim3(NLIDX * BATCH, HEADS), 192>>>(pqkv, pah, pal);
        gemm_ep1<<<gE, 512, DSMEM_BYTES>>>(pah, pal, pwh + base + (size_t)3 * WQKV,
                                           pwl + base + (size_t)3 * WQKV,
                                           bo + l * EMB, px, pafh, pafl, EMB, EMB);
        ln_split_kernel<<<TOK / 8, 256>>>(px, pah, pal, l2g + l * EMB, l2b + l * EMB);
        gemm_ep2<<<gF, 512, DSMEM_BYTES>>>(pah, pal, pwh + base + (size_t)4 * WQKV,
                                           pwl + base + (size_t)4 * WQKV,
                                           b1 + l * FF, px, pafh, pafl, FF, EMB);
        gemm_ep1<<<gE, 512, DSMEM_BYTES>>>(pafh, pafl, pwh + base + (size_t)4 * WQKV + WFFN,
                                           pwl + base + (size_t)4 * WQKV + WFFN,
                                           b2 + l * EMB, px, pafh, pafl, EMB, FF);
    }
    ln_split_kernel<<<TOK / 8, 256>>>(px, pah, pal, lfg, lfb);
    outproj_kernel<<<NLIDX * BATCH, 256>>>(pah, pal, Wout, bout, plog);
    match_kernel<<<NLIDX, 1024, 131072>>>(plog, tg, plos);
    final_mean_kernel<<<1, 32>>>(plos, (float*)d_out);
}

// round 16
// speedup vs baseline: 1.5347x; 1.5347x over previous
#include <cuda_runtime.h>
#include <cuda_bf16.h>
#include <math.h>
#include <stdint.h>

// ---------------- problem constants ----------------
#define BATCH  128
#define LSEQ   16
#define EMB    768
#define DHALF  384
#define HEADS  12
#define HDIM   64
#define NL     6
#define SEQ    12
#define NLIDX  15
#define FF     3072
#define TOK    (NLIDX * BATCH * SEQ)        // 23040
#define TE     (TOK * EMB)                  // 17694720

#define WQKV   (EMB * EMB)                  // 589824
#define WFFN   (EMB * FF)                   // 2359296
#define WLAYER (4 * WQKV + 2 * WFFN)        // 7077888
#define NQKV   (3 * EMB)                    // 2304

// GEMM tiling: 128x256 tile, BK=32, 3-stage cp.async pipeline, 512 threads
#define BM 128
#define BN 256
#define BKT 32
// stage: Ah 12288 + Al 12288 + Bh 24576 + Bl 24576 = 73728
#define STAGE_BYTES 73728
#define NSTAGE 3
#define DSMEM_BYTES (NSTAGE * STAGE_BYTES)   // 221184

// ---------------- scratch (device globals; no cudaMalloc allowed) ----------------
__device__ float g_x[TE];                          // fp32 residual stream
__device__ float g_qkv[(size_t)TOK * NQKV];        // fused qkv output (fp32)
__device__ __nv_bfloat16 g_ah[(size_t)TOK * EMB];  // 768-wide GEMM input hi
__device__ __nv_bfloat16 g_al[(size_t)TOK * EMB];  // 768-wide GEMM input lo
__device__ __nv_bfloat16 g_afh[(size_t)TOK * FF];  // 3072-wide GEMM input hi
__device__ __nv_bfloat16 g_afl[(size_t)TOK * FF];  // 3072-wide GEMM input lo
__device__ __nv_bfloat16 g_wh[(size_t)NL * WLAYER];// transposed weights hi  [N][K]
__device__ __nv_bfloat16 g_wl[(size_t)NL * WLAYER];// transposed weights lo
__device__ float g_bqkv[NL * NQKV];
__device__ float g_logits[NLIDX * BATCH * 3];
__device__ float g_losses[NLIDX];

// ---------------- helpers ----------------
static __device__ __forceinline__ unsigned int smem_u32(const void* p) {
    unsigned int a;
    asm("{ .reg .u64 t; cvta.to.shared.u64 t, %1; cvt.u32.u64 %0, t; }"
        : "=r"(a) : "l"(p));
    return a;
}
static __device__ __forceinline__ void cp16(unsigned int dst, const void* src) {
    asm volatile("cp.async.cg.shared.global [%0], [%1], 16;" :: "r"(dst), "l"(src));
}
static __device__ __forceinline__ void cp_commit() {
    asm volatile("cp.async.commit_group;" ::: "memory");
}
static __device__ __forceinline__ void cp_wait1() {
    asm volatile("cp.async.wait_group 1;" ::: "memory");
}
static __device__ __forceinline__ void cp_wait0() {
    asm volatile("cp.async.wait_group 0;" ::: "memory");
}
static __device__ __forceinline__ void ldsm4(unsigned int* r, unsigned int addr) {
    asm volatile("ldmatrix.sync.aligned.m8n8.x4.shared.b16 {%0,%1,%2,%3}, [%4];"
                 : "=r"(r[0]), "=r"(r[1]), "=r"(r[2]), "=r"(r[3]) : "r"(addr));
}
static __device__ __forceinline__ void mma_bf16(float* c, const unsigned int* a,
                                                unsigned int b0, unsigned int b1) {
    asm volatile(
        "mma.sync.aligned.m16n8k16.row.col.f32.bf16.bf16.f32 "
        "{%0,%1,%2,%3}, {%4,%5,%6,%7}, {%8,%9}, {%0,%1,%2,%3};"
        : "+f"(c[0]), "+f"(c[1]), "+f"(c[2]), "+f"(c[3])
        : "r"(a[0]), "r"(a[1]), "r"(a[2]), "r"(a[3]), "r"(b0), "r"(b1));
}
static __device__ __forceinline__ void split_bf16(float v, __nv_bfloat16& h, __nv_bfloat16& l) {
    h = __float2bfloat16_rn(v);
    l = __float2bfloat16_rn(v - __bfloat162float(h));
}
static __device__ __forceinline__ unsigned int pack_bf2(__nv_bfloat16 a, __nv_bfloat16 b) {
    __nv_bfloat162 p; p.x = a; p.y = b;
    return *reinterpret_cast<unsigned int*>(&p);
}

// ---------------- batched weight transpose+split ----------------
__global__ __launch_bounds__(256) void wtrans_sq_kernel(
    const float* __restrict__ Wq, const float* __restrict__ Wk,
    const float* __restrict__ Wv, const float* __restrict__ Wo,
    __nv_bfloat16* __restrict__ hi, __nv_bfloat16* __restrict__ lo)
{
    __shared__ float tile[32][33];
    int z = blockIdx.z;
    int l = z >> 2, m = z & 3;
    const float* W = (m == 0) ? Wq : (m == 1) ? Wk : (m == 2) ? Wv : Wo;
    W += (size_t)l * WQKV;
    size_t obase = (size_t)l * WLAYER + (size_t)m * WQKV;

    int n0 = blockIdx.x * 32, k0 = blockIdx.y * 32;
    int tx = threadIdx.x & 31, ty = threadIdx.x >> 5;
#pragma unroll
    for (int j = 0; j < 4; ++j)
        tile[ty + j * 8][tx] = W[(size_t)(k0 + ty + j * 8) * EMB + n0 + tx];
    __syncthreads();
#pragma unroll
    for (int j = 0; j < 4; ++j) {
        int n = ty + j * 8;
        float v = tile[tx][n];
        __nv_bfloat16 h, l2;
        split_bf16(v, h, l2);
        size_t o = obase + (size_t)(n0 + n) * EMB + k0 + tx;
        hi[o] = h;
        lo[o] = l2;
    }
}

__global__ __launch_bounds__(256) void wtrans_f1_kernel(
    const float* __restrict__ W1, __nv_bfloat16* __restrict__ hi,
    __nv_bfloat16* __restrict__ lo)
{
    __shared__ float tile[32][33];
    int l = blockIdx.z;
    const float* W = W1 + (size_t)l * WFFN;
    size_t obase = (size_t)l * WLAYER + (size_t)4 * WQKV;

    int n0 = blockIdx.x * 32, k0 = blockIdx.y * 32;
    int tx = threadIdx.x & 31, ty = threadIdx.x >> 5;
#pragma unroll
    for (int j = 0; j < 4; ++j)
        tile[ty + j * 8][tx] = W[(size_t)(k0 + ty + j * 8) * FF + n0 + tx];
    __syncthreads();
#pragma unroll
    for (int j = 0; j < 4; ++j) {
        int n = ty + j * 8;
        float v = tile[tx][n];
        __nv_bfloat16 h, l2;
        split_bf16(v, h, l2);
        size_t o = obase + (size_t)(n0 + n) * EMB + k0 + tx;
        hi[o] = h;
        lo[o] = l2;
    }
}

__global__ __launch_bounds__(256) void wtrans_f2_kernel(
    const float* __restrict__ W2, __nv_bfloat16* __restrict__ hi,
    __nv_bfloat16* __restrict__ lo)
{
    __shared__ float tile[32][33];
    int l = blockIdx.z;
    const float* W = W2 + (size_t)l * WFFN;
    size_t obase = (size_t)l * WLAYER + (size_t)4 * WQKV + WFFN;

    int n0 = blockIdx.x * 32, k0 = blockIdx.y * 32;
    int tx = threadIdx.x & 31, ty = threadIdx.x >> 5;
#pragma unroll
    for (int j = 0; j < 4; ++j)
        tile[ty + j * 8][tx] = W[(size_t)(k0 + ty + j * 8) * EMB + n0 + tx];
    __syncthreads();
#pragma unroll
    for (int j = 0; j < 4; ++j) {
        int n = ty + j * 8;
        float v = tile[tx][n];
        __nv_bfloat16 h, l2;
        split_bf16(v, h, l2);
        size_t o = obase + (size_t)(n0 + n) * FF + k0 + tx;
        hi[o] = h;
        lo[o] = l2;
    }
}

// ---------------- input assembly (+ fused qkv bias concat in tail blocks) ----------------
#define ASM_TOTAL (TE + NL * NQKV)
__global__ __launch_bounds__(256) void assemble_kernel(
    const float* __restrict__ X, const float* __restrict__ targets,
    const float* __restrict__ omegas, const float* __restrict__ phases,
    const int* __restrict__ perms, float* __restrict__ xout,
    const float* __restrict__ bq, const float* __restrict__ bk,
    const float* __restrict__ bv, float* __restrict__ bqkv)
{
    int idx = blockIdx.x * blockDim.x + threadIdx.x;
    if (idx >= ASM_TOTAL) return;
    if (idx >= TE) {
        int k = idx - TE;
        int l = k / NQKV, n = k % NQKV;
        float v;
        if (n < EMB) v = bq[l * EMB + n];
        else if (n < 2 * EMB) v = bk[l * EMB + n - EMB];
        else v = bv[l * EMB + n - 2 * EMB];
        bqkv[k] = v;
        return;
    }
    int e = idx % EMB;
    int t = idx / EMB;
    int s = t % SEQ;
    int b = (t / SEQ) % BATCH;
    int lidx = t / (SEQ * BATCH);
    int sb = perms[lidx * BATCH + b];

    float val;
    if (s < 3) {
        int c = s;
        int ti = (e < DHALF) ? (15 - lidx) : (14 - lidx);
        int d  = (e < DHALF) ? e : (e - DHALF);
        float xv = X[(sb * LSEQ + ti) * 3 + c];
        val = cosf(xv * omegas[c * DHALF + d] + phases[c * DHALF + d]);
    } else if (s < 6) {
        int c = s - 3;
        int ti = (16 - lidx) % 16;
        val = targets[(sb * LSEQ + ti) * 3 + c];
    } else {
        val = (float)(15 - lidx);
    }
    xout[idx] = val;
}

// ---------------- layernorm: warp per token, shuffle-only reductions ----------------
__global__ __launch_bounds__(256) void ln_split_kernel(
    const float* __restrict__ in, __nv_bfloat16* __restrict__ oh,
    __nv_bfloat16* __restrict__ ol, const float* __restrict__ gam,
    const float* __restrict__ bet)
{
    int tok  = blockIdx.x * 8 + (threadIdx.x >> 5);
    int lane = threadIdx.x & 31;
    const float* x = in + (size_t)tok * EMB;

    float v[24];
    float s = 0.0f;
#pragma unroll
    for (int j = 0; j < 24; ++j) {
        v[j] = x[lane + j * 32];
        s += v[j];
    }
#pragma unroll
    for (int o = 16; o > 0; o >>= 1) s += __shfl_xor_sync(0xffffffffu, s, o);
    float mu = s * (1.0f / EMB);

    float var = 0.0f;
#pragma unroll
    for (int j = 0; j < 24; ++j) {
        v[j] -= mu;
        var += v[j] * v[j];
    }
#pragma unroll
    for (int o = 16; o > 0; o >>= 1) var += __shfl_xor_sync(0xffffffffu, var, o);
    float rs = rsqrtf(var * (1.0f / EMB) + 1e-3f);

    size_t base = (size_t)tok * EMB;
#pragma unroll
    for (int j = 0; j < 24; ++j) {
        int e = lane + j * 32;
        float r = v[j] * rs * gam[e] + bet[e];
        __nv_bfloat16 h, l;
        split_bf16(r, h, l);
        oh[base + e] = h;
        ol[base + e] = l;
    }
}

// ---------------- bf16x3 mma.sync GEMM, 128x256 tile, 512 thr, 3-stage ----------------
// C[M, Ntot] = A[M, K] @ Wt[Ntot, K]^T, all operands pre-split bf16 hi/lo.
// 16 warps as 4(m) x 4(n), warp tile 32x64. One __syncthreads per stage.
// Two-pass B fragments per chunk (Bh pass: HH+LH; Bl pass: HL) to keep live
// registers ~116 < 128 (round-14 spill fix).
// EPI 0: Cf = acc + bias ; 1: Cf += acc + bias ; 2: Ch/Cl = split(relu(acc + bias))
template <int EPI>
static __device__ __forceinline__ void gemm_body(
    const __nv_bfloat16* __restrict__ Ah, const __nv_bfloat16* __restrict__ Al,
    const __nv_bfloat16* __restrict__ Bh, const __nv_bfloat16* __restrict__ Bl,
    const float* __restrict__ bias, float* __restrict__ Cf,
    __nv_bfloat16* __restrict__ Ch, __nv_bfloat16* __restrict__ Cl,
    int Ntot, int K)
{
    extern __shared__ __align__(16) char dsm[];
    const int t = threadIdx.x;
    const int lane = t & 31, wid = t >> 5;
    const int wm = wid >> 2, wn = wid & 3;
    const int row0 = blockIdx.y * BM, col0 = blockIdx.x * BN;
    const unsigned int smem = smem_u32(dsm);

    float acc[2][8][4];
#pragma unroll
    for (int i = 0; i < 2; ++i)
#pragma unroll
        for (int j = 0; j < 8; ++j)
#pragma unroll
            for (int k = 0; k < 4; ++k) acc[i][j][k] = 0.0f;

    // cp.async mapping: 512 threads, 6 cp16 each (A hi/lo at row rr; B rows rr, rr+128 hi/lo)
    const int seg   = t & 1;
    const int chunk = (t >> 1) & 1;
    const int rr    = t >> 2;                    // 0..127
    const int koff0 = chunk * 16 + seg * 8;

    auto load_stage = [&](int kt, int stg) {
        unsigned int sb = smem + stg * STAGE_BYTES;
        int koff = kt * BKT + koff0;
        // A rows
#pragma unroll
        for (int hl = 0; hl < 2; ++hl) {
            const __nv_bfloat16* src = (hl ? Al : Ah) + (size_t)(row0 + rr) * K + koff;
            cp16(sb + hl * 12288 + chunk * 6144 + rr * 48 + seg * 16, src);
        }
        // B rows
#pragma unroll
        for (int i = 0; i < 4; ++i) {
            int hl = i & 1, rh = i >> 1;
            int r = rh * 128 + rr;
            const __nv_bfloat16* src = (hl ? Bl : Bh) + (size_t)(col0 + r) * K + koff;
            cp16(sb + 24576 + hl * 24576 + chunk * 12288 + r * 48 + seg * 16, src);
        }
        cp_commit();
    };

    // ldmatrix base addresses
    const unsigned int aHb = smem + (wm * 32 + (lane & 15)) * 48 + ((lane >> 4) << 4);
    const unsigned int bHb = smem + 24576 +
        (wn * 64 + (lane & 7) + ((lane >> 4) << 3)) * 48 + (((lane >> 3) & 1) << 4);

    const int nst = K / BKT;
    load_stage(0, 0);
    load_stage(1, 1);

    for (int st = 0; st < nst; ++st) {
        if (st + 1 < nst) cp_wait1(); else cp_wait0();
        __syncthreads();
        if (st + 2 < nst) load_stage(st + 2, (st + 2) % NSTAGE);
        unsigned int so = (st % NSTAGE) * STAGE_BYTES;
#pragma unroll
        for (int ch = 0; ch < 2; ++ch) {
            unsigned int aco = so + ch * 6144;
            unsigned int bco = so + ch * 12288;
            unsigned int Afh[2][4], Afl[2][4];
            ldsm4(Afh[0], aHb + aco);
            ldsm4(Afh[1], aHb + aco + 768);
            ldsm4(Afl[0], aHb + aco + 12288);
            ldsm4(Afl[1], aHb + aco + 12288 + 768);
            unsigned int Bf[4][4];
            // ---- pass 1: Bh fragments -> HH and LH terms ----
#pragma unroll
            for (int f = 0; f < 4; ++f)
                ldsm4(Bf[f], bHb + bco + f * 768);
#pragma unroll
            for (int mi = 0; mi < 2; ++mi) {
#pragma unroll
                for (int f = 0; f < 4; ++f)
#pragma unroll
                    for (int q = 0; q < 2; ++q)
                        mma_bf16(acc[mi][f * 2 + q], Afh[mi], Bf[f][2 * q], Bf[f][2 * q + 1]);
#pragma unroll
                for (int f = 0; f < 4; ++f)
#pragma unroll
                    for (int q = 0; q < 2; ++q)
                        mma_bf16(acc[mi][f * 2 + q], Afl[mi], Bf[f][2 * q], Bf[f][2 * q + 1]);
            }
            // ---- pass 2: Bl fragments (reuse Bf regs) -> HL term ----
#pragma unroll
            for (int f = 0; f < 4; ++f)
                ldsm4(Bf[f], bHb + bco + 24576 + f * 768);
#pragma unroll
            for (int mi = 0; mi < 2; ++mi)
#pragma unroll
                for (int f = 0; f < 4; ++f)
#pragma unroll
                    for (int q = 0; q < 2; ++q)
                        mma_bf16(acc[mi][f * 2 + q], Afh[mi], Bf[f][2 * q], Bf[f][2 * q + 1]);
        }
    }

    // ---- epilogue ----
    const int rbase = row0 + wm * 32 + (lane >> 2);
    const int cbase = col0 + wn * 64 + (lane & 3) * 2;
#pragma unroll
    for (int ni = 0; ni < 8; ++ni) {
        int cb = cbase + ni * 8;
        float2 bi = *(const float2*)&bias[cb];
#pragma unroll
        for (int mi = 0; mi < 2; ++mi) {
            float* c = acc[mi][ni];
            size_t o0 = (size_t)(rbase + mi * 16) * Ntot + cb;
            size_t o1 = o0 + (size_t)8 * Ntot;
            if (EPI == 2) {
                float v00 = fmaxf(c[0] + bi.x, 0.0f), v01 = fmaxf(c[1] + bi.y, 0.0f);
                float v10 = fmaxf(c[2] + bi.x, 0.0f), v11 = fmaxf(c[3] + bi.y, 0.0f);
                __nv_bfloat16 h00, l00, h01, l01, h10, l10, h11, l11;
                split_bf16(v00, h00, l00);
                split_bf16(v01, h01, l01);
                split_bf16(v10, h10, l10);
                split_bf16(v11, h11, l11);
                *(unsigned int*)&Ch[o0] = pack_bf2(h00, h01);
                *(unsigned int*)&Cl[o0] = pack_bf2(l00, l01);
                *(unsigned int*)&Ch[o1] = pack_bf2(h10, h11);
                *(unsigned int*)&Cl[o1] = pack_bf2(l10, l11);
            } else {
                float2 v0 = make_float2(c[0] + bi.x, c[1] + bi.y);
                float2 v1 = make_float2(c[2] + bi.x, c[3] + bi.y);
                if (EPI == 1) {
                    float2 p0 = *(float2*)&Cf[o0], p1 = *(float2*)&Cf[o1];
                    v0.x += p0.x; v0.y += p0.y;
                    v1.x += p1.x; v1.y += p1.y;
                }
                *(float2*)&Cf[o0] = v0;
                *(float2*)&Cf[o1] = v1;
            }
        }
    }
}

// plain-named wrappers
__global__ __launch_bounds__(512, 1) void gemm_ep0(
    const __nv_bfloat16* __restrict__ Ah, const __nv_bfloat16* __restrict__ Al,
    const __nv_bfloat16* __restrict__ Bh, const __nv_bfloat16* __restrict__ Bl,
    const float* __restrict__ bias, float* __restrict__ Cf,
    __nv_bfloat16* __restrict__ Ch, __nv_bfloat16* __restrict__ Cl, int Ntot, int K)
{ gemm_body<0>(Ah, Al, Bh, Bl, bias, Cf, Ch, Cl, Ntot, K); }

__global__ __launch_bounds__(512, 1) void gemm_ep1(
    const __nv_bfloat16* __restrict__ Ah, const __nv_bfloat16* __restrict__ Al,
    const __nv_bfloat16* __restrict__ Bh, const __nv_bfloat16* __restrict__ Bl,
    const float* __restrict__ bias, float* __restrict__ Cf,
    __nv_bfloat16* __restrict__ Ch, __nv_bfloat16* __restrict__ Cl, int Ntot, int K)
{ gemm_body<1>(Ah, Al, Bh, Bl, bias, Cf, Ch, Cl, Ntot, K); }

__global__ __launch_bounds__(512, 1) void gemm_ep2(
    const __nv_bfloat16* __restrict__ Ah, const __nv_bfloat16* __restrict__ Al,
    const __nv_bfloat16* __restrict__ Bh, const __nv_bfloat16* __restrict__ Bl,
    const float* __restrict__ bias, float* __restrict__ Cf,
    __nv_bfloat16* __restrict__ Ch, __nv_bfloat16* __restrict__ Cl, int Ntot, int K)
{ gemm_body<2>(Ah, Al, Bh, Bl, bias, Cf, Ch, Cl, Ntot, K); }

// ---------------- attention: reads fused qkv (stride 2304), writes hi/lo o ----------------
__global__ __launch_bounds__(192) void attn_kernel(
    const float* __restrict__ qkv, __nv_bfloat16* __restrict__ oh,
    __nv_bfloat16* __restrict__ ol)
{
    int inst = blockIdx.x;
    int h    = blockIdx.y;
    int base = inst * SEQ;
    int tid  = threadIdx.x;

    __shared__ float qs[SEQ][HDIM], ks[SEQ][HDIM], vs[SEQ][HDIM];
    __shared__ float sc[SEQ][SEQ], ps[SEQ][SEQ];

    for (int idx = tid; idx < SEQ * HDIM; idx += 192) {
        int s = idx >> 6, d = idx & 63;
        size_t g = (size_t)(base + s) * NQKV + h * HDIM + d;
        qs[s][d] = qkv[g];
        ks[s][d] = qkv[g + EMB];
        vs[s][d] = qkv[g + 2 * EMB];
    }
    __syncthreads();

    if (tid < SEQ * SEQ) {
        int i = tid / SEQ, j = tid % SEQ;
        float a = 0.0f;
#pragma unroll
        for (int d = 0; d < HDIM; ++d) a += qs[i][d] * ks[j][d];
        sc[i][j] = a * 0.125f;
    }
    __syncthreads();

    if (tid < SEQ) {
        float mx = -1e30f;
#pragma unroll
        for (int j = 0; j < SEQ; ++j) mx = fmaxf(mx, sc[tid][j]);
        float sum = 0.0f;
#pragma unroll
        for (int j = 0; j < SEQ; ++j) { float ev = expf(sc[tid][j] - mx); ps[tid][j] = ev; sum += ev; }
        float inv = 1.0f / sum;
#pragma unroll
        for (int j = 0; j < SEQ; ++j) ps[tid][j] *= inv;
    }
    __syncthreads();

    for (int idx = tid; idx < SEQ * HDIM; idx += 192) {
        int i = idx >> 6, d = idx & 63;
        float a = 0.0f;
#pragma unroll
        for (int j = 0; j < SEQ; ++j) a += ps[i][j] * vs[j][d];
        __nv_bfloat16 hh, ll;
        split_bf16(a, hh, ll);
        size_t g = (size_t)(base + i) * EMB + h * HDIM + d;
        oh[g] = hh;
        ol[g] = ll;
    }
}

// ---------------- output projection (reads hi+lo reconstructed) ----------------
__global__ __launch_bounds__(256) void outproj_kernel(
    const __nv_bfloat16* __restrict__ hh, const __nv_bfloat16* __restrict__ hl,
    const float* __restrict__ Wout, const float* __restrict__ bout,
    float* __restrict__ logits)
{
    __shared__ float r0[256], r1[256], r2[256];
    int inst = blockIdx.x;
    int tid = threadIdx.x;
    size_t base = (size_t)inst * (SEQ * EMB);
    float a0 = 0, a1 = 0, a2 = 0;
    for (int kk = tid; kk < SEQ * EMB; kk += 256) {
        float x = __bfloat162float(hh[base + kk]) + __bfloat162float(hl[base + kk]);
        const float* w = Wout + kk * 3;
        a0 += x * w[0]; a1 += x * w[1]; a2 += x * w[2];
    }
    r0[tid] = a0; r1[tid] = a1; r2[tid] = a2;
    __syncthreads();
    for (int s = 128; s > 0; s >>= 1) {
        if (tid < s) { r0[tid] += r0[tid + s]; r1[tid] += r1[tid + s]; r2[tid] += r2[tid + s]; }
        __syncthreads();
    }
    if (tid == 0) {
        logits[inst * 3 + 0] = r0[0] + bout[0];
        logits[inst * 3 + 1] = r1[0] + bout[1];
        logits[inst * 3 + 2] = r2[0] + bout[2];
    }
}

// ---------------- greedy matching + loss ----------------
__global__ __launch_bounds__(1024) void match_kernel(
    const float* __restrict__ logits, const float* __restrict__ targets,
    float* __restrict__ losses)
{
    extern __shared__ unsigned long long keys[];
    __shared__ int rowm[BATCH];
    __shared__ unsigned long long warpmin[32];
    __shared__ float red[1024];

    int lidx = blockIdx.x;
    int tid = threadIdx.x;
    int tref = 15 - lidx;
    const float* lg = logits + lidx * BATCH * 3;

    for (int e = tid; e < BATCH * BATCH; e += 1024) {
        int i = e >> 7, j = e & 127;
        float dx = lg[i * 3 + 0] - targets[(j * LSEQ + tref) * 3 + 0];
        float dy = lg[i * 3 + 1] - targets[(j * LSEQ + tref) * 3 + 1];
        float dz = lg[i * 3 + 2] - targets[(j * LSEQ + tref) * 3 + 2];
        float c = sqrtf(dx * dx + dy * dy + dz * dz + 1e-12f);
        keys[e] = ((unsigned long long)__float_as_uint(c) << 32) | (unsigned int)e;
    }
    __syncthreads();

    for (int r = 0; r < BATCH; ++r) {
        unsigned long long m = ~0ull;
        for (int e = tid; e < BATCH * BATCH; e += 1024) {
            unsigned long long kk = keys[e];
            m = (kk < m) ? kk : m;
        }
#pragma unroll
        for (int o = 16; o > 0; o >>= 1) {
            unsigned long long other = __shfl_down_sync(0xffffffffu, m, o);
            m = (other < m) ? other : m;
        }
        if ((tid & 31) == 0) warpmin[tid >> 5] = m;
        __syncthreads();
        if (tid < 32) {
            unsigned long long mm = warpmin[tid];
#pragma unroll
            for (int o = 16; o > 0; o >>= 1) {
                unsigned long long other = __shfl_down_sync(0xffffffffu, mm, o);
                mm = (other < mm) ? other : mm;
            }
            if (tid == 0) warpmin[0] = mm;
        }
        __syncthreads();
        unsigned long long best = warpmin[0];
        int e = (int)(best & 0xffffffffull);
        int bi = e >> 7, bj = e & 127;
        if (tid < BATCH) {
            keys[bi * BATCH + tid] = ~0ull;
            keys[tid * BATCH + bj] = ~0ull;
        }
        if (tid == 0) rowm[bi] = bj;
        __syncthreads();
    }

    float part = 0.0f;
    if (tid < BATCH * 3) {
        int i = tid / 3, c = tid % 3;
        float d = lg[rowm[i] * 3 + c] - targets[(i * LSEQ + tref) * 3 + c];
        part = d * d;
    }
    red[tid] = part;
    __syncthreads();
    for (int s = 512; s > 0; s >>= 1) {
        if (tid < s) red[tid] += red[tid + s];
        __syncthreads();
    }
    if (tid == 0) losses[lidx] = red[0] * (1.0f / (BATCH * 3));
}

__global__ void final_mean_kernel(const float* __restrict__ losses, float* __restrict__ out)
{
    if (threadIdx.x == 0 && blockIdx.x == 0) {
        float s = 0.0f;
        for (int i = 0; i < NLIDX; ++i) s += losses[i];
        out[0] = s * (1.0f / NLIDX);
    }
}

// ---------------- launch ----------------
extern "C" void kernel_launch(void* const* d_in, const int* in_sizes, int n_in,
                              void* d_out, int out_size)
{
    (void)in_sizes; (void)n_in; (void)out_size;
    const float* X    = (const float*)d_in[0];
    const float* tg   = (const float*)d_in[1];
    const float* om   = (const float*)d_in[2];
    const float* ph   = (const float*)d_in[3];
    const int*   pm   = (const int*)  d_in[4];
    const float* Wq   = (const float*)d_in[5];
    const float* bq   = (const float*)d_in[6];
    const float* Wk   = (const float*)d_in[7];
    const float* bk   = (const float*)d_in[8];
    const float* Wv   = (const float*)d_in[9];
    const float* bv   = (const float*)d_in[10];
    const float* Wo   = (const float*)d_in[11];
    const float* bo   = (const float*)d_in[12];
    const float* l1g  = (const float*)d_in[13];
    const float* l1b  = (const float*)d_in[14];
    const float* l2g  = (const float*)d_in[15];
    const float* l2b  = (const float*)d_in[16];
    const float* W1   = (const float*)d_in[17];
    const float* b1   = (const float*)d_in[18];
    const float* W2   = (const float*)d_in[19];
    const float* b2   = (const float*)d_in[20];
    const float* lfg  = (const float*)d_in[21];
    const float* lfb  = (const float*)d_in[22];
    const float* Wout = (const float*)d_in[23];
    const float* bout = (const float*)d_in[24];

    float *px, *pqkv, *pbqkv, *plog, *plos;
    __nv_bfloat16 *pah, *pal, *pafh, *pafl, *pwh, *pwl;
    cudaGetSymbolAddress((void**)&px,    g_x);
    cudaGetSymbolAddress((void**)&pqkv,  g_qkv);
    cudaGetSymbolAddress((void**)&pbqkv, g_bqkv);
    cudaGetSymbolAddress((void**)&plog,  g_logits);
    cudaGetSymbolAddress((void**)&plos,  g_losses);
    cudaGetSymbolAddress((void**)&pah,   g_ah);
    cudaGetSymbolAddress((void**)&pal,   g_al);
    cudaGetSymbolAddress((void**)&pafh,  g_afh);
    cudaGetSymbolAddress((void**)&pafl,  g_afl);
    cudaGetSymbolAddress((void**)&pwh,   g_wh);
    cudaGetSymbolAddress((void**)&pwl,   g_wl);

    cudaFuncSetAttribute(match_kernel, cudaFuncAttributeMaxDynamicSharedMemorySize, 131072);
    cudaFuncSetAttribute(gemm_ep0, cudaFuncAttributeMaxDynamicSharedMemorySize, DSMEM_BYTES);
    cudaFuncSetAttribute(gemm_ep1, cudaFuncAttributeMaxDynamicSharedMemorySize, DSMEM_BYTES);
    cudaFuncSetAttribute(gemm_ep2, cudaFuncAttributeMaxDynamicSharedMemorySize, DSMEM_BYTES);

    // prep
    wtrans_sq_kernel<<<dim3(EMB / 32, EMB / 32, NL * 4), 256>>>(Wq, Wk, Wv, Wo, pwh, pwl);
    wtrans_f1_kernel<<<dim3(FF / 32, EMB / 32, NL), 256>>>(W1, pwh, pwl);
    wtrans_f2_kernel<<<dim3(EMB / 32, FF / 32, NL), 256>>>(W2, pwh, pwl);
    assemble_kernel<<<(ASM_TOTAL + 255) / 256, 256>>>(X, tg, om, ph, pm, px, bq, bk, bv, pbqkv);

    dim3 gQKV(NQKV / BN, TOK / BM);   // (9, 180)
    dim3 gE(EMB / BN, TOK / BM);      // (3, 180)
    dim3 gF(FF / BN, TOK / BM);       // (12, 180)
    for (int l = 0; l < NL; ++l) {
        size_t base = (size_t)l * WLAYER;
        ln_split_kernel<<<TOK / 8, 256>>>(px, pah, pal, l1g + l * EMB, l1b + l * EMB);
        gemm_ep0<<<gQKV, 512, DSMEM_BYTES>>>(pah, pal, pwh + base, pwl + base,
                                             pbqkv + l * NQKV, pqkv, pafh, pafl, NQKV, EMB);
        attn_kernel<<<dim3(NLIDX * BATCH, HEADS), 192>>>(pqkv, pah, pal);
        gemm_ep1<<<gE, 512, DSMEM_BYTES>>>(pah, pal, pwh + base + (size_t)3 * WQKV,
                                           pwl + base + (size_t)3 * WQKV,
                                           bo + l * EMB, px, pafh, pafl, EMB, EMB);
        ln_split_kernel<<<TOK / 8, 256>>>(px, pah, pal, l2g + l * EMB, l2b + l * EMB);
        gemm_ep2<<<gF, 512, DSMEM_BYTES>>>(pah, pal, pwh + base + (size_t)4 * WQKV,
                                           pwl + base + (size_t)4 * WQKV,
                                           b1 + l * FF, px, pafh, pafl, FF, EMB);
        gemm_ep1<<<gE, 512, DSMEM_BYTES>>>(pafh, pafl, pwh + base + (size_t)4 * WQKV + WFFN,
                                           pwl + base + (size_t)4 * WQKV + WFFN,
                                           b2 + l * EMB, px, pafh, pafl, EMB, FF);
    }
    ln_split_kernel<<<TOK / 8, 256>>>(px, pah, pal, lfg, lfb);
    outproj_kernel<<<NLIDX * BATCH, 256>>>(pah, pal, Wout, bout, plog);
    match_kernel<<<NLIDX, 1024, 131072>>>(plog, tg, plos);
    final_mean_kernel<<<1, 32>>>(plos, (float*)d_out);
}